// round 13
// baseline (speedup 1.0000x reference)
#include <cuda_runtime.h>
#include <cstdint>

// DbrxRouter: x[T,H] fp32 @ W[E=16,H]^T -> logits; softmax -> top4 -> /sum(top4)
// Outputs concatenated float32: weights [T,4] then indices [T,4] (as float).
//
// CTA = 128 thr / 4 warps / 16 tokens. Dual cp.async rings (x and W) as R12.
// NEW: warps are COLUMN-sliced over each chunk (warp w owns float4 cols
// 4w..4w+3 for all 16 tokens x 16 experts). Lane = (eg,tg,ch) 4x4 register
// tile -> every x/W LDS.128 has only 8 distinct addresses (128B) = 1 wavefront
// (4-way broadcast), and no warp re-reads another warp's W. CTA-chunk LDS
// wavefronts drop 160 -> 64; total L1 demand -35%. Col-partial logits are
// combined in a tiny smem epilogue overlaid on the dead ring.

#define NE      16
#define TOKC    16            // tokens per CTA
#define STAGES  5
#define PRO     3             // prologue depth
#define CH4     16            // float4 per row per chunk (256B)

__device__ __forceinline__ void fma2(unsigned long long& d,
                                     unsigned long long a,
                                     unsigned long long b) {
    asm("fma.rn.f32x2 %0, %1, %2, %0;" : "+l"(d) : "l"(a), "l"(b));
}
__device__ __forceinline__ float lo_f(unsigned long long v) {
    return __uint_as_float((unsigned)(v & 0xffffffffull));
}
__device__ __forceinline__ float hi_f(unsigned long long v) {
    return __uint_as_float((unsigned)(v >> 32));
}
__device__ __forceinline__ void cp16(uint32_t dst, const void* src) {
    asm volatile("cp.async.cg.shared.global [%0], [%1], 16;"
                 :: "r"(dst), "l"(src) : "memory");
}

__global__ __launch_bounds__(128, 4)
void router_kernel(const float* __restrict__ x, const float* __restrict__ w,
                   float* __restrict__ out, int T, int H4, int idx_off)
{
    // 5 x (4KB x + 4KB W) = 40KB static smem. xs is reused for the epilogue
    // reduction scratch (4KB) after the mainloop.
    __shared__ __align__(16) ulonglong2 xs[STAGES][TOKC][CH4];
    __shared__ __align__(16) ulonglong2 ws[STAGES][NE][CH4];

    const int tid  = threadIdx.x;
    const int wid  = tid >> 5;
    const int lane = tid & 31;
    const int eg   = lane >> 3;          // expert group: experts 4*eg..4*eg+3
    const int tg   = (lane >> 1) & 3;    // token group:  tokens  4*tg..4*tg+3
    const int ch   = lane & 1;           // col half within warp's slice
    const int ct0  = blockIdx.x * TOKC;  // CTA's first token
    if (ct0 >= T) return;

    const ulonglong2* __restrict__ x2 = reinterpret_cast<const ulonglong2*>(x);
    const ulonglong2* __restrict__ w2 = reinterpret_cast<const ulonglong2*>(w);

    // ---- producer mapping: thread -> (row, off) and (row, off+8) ----
    const int crow = tid >> 3;           // 0..15 (token slot / W row)
    const int coff = tid & 7;            // 0..7
    const ulonglong2* srcx = x2 + (size_t)min(ct0 + crow, T - 1) * H4 + coff;
    const ulonglong2* srcw = w2 + (size_t)crow * H4 + coff;

    const uint32_t xbase = (uint32_t)__cvta_generic_to_shared(&xs[0][0][0]);
    const uint32_t wbase = (uint32_t)__cvta_generic_to_shared(&ws[0][0][0]);
    const uint32_t stage_b = TOKC * CH4 * 16;            // 4096
    const uint32_t dx = xbase + (uint32_t)((crow * CH4 + coff) * 16);
    const uint32_t dw = wbase + (uint32_t)((crow * CH4 + coff) * 16);

    const int NCH = H4 / CH4;            // 96 chunks

    // Prologue: fill PRO stages.
    #pragma unroll
    for (int p = 0; p < PRO; ++p) {
        const uint32_t sb = (uint32_t)p * stage_b;
        cp16(dx + sb,            srcx + p * CH4);
        cp16(dx + sb + 8 * 16,   srcx + p * CH4 + 8);
        cp16(dw + sb,            srcw + p * CH4);
        cp16(dw + sb + 8 * 16,   srcw + p * CH4 + 8);
        asm volatile("cp.async.commit_group;" ::: "memory");
    }

    unsigned long long acc[4][4];        // [token-in-group][expert-in-group]
    #pragma unroll
    for (int t = 0; t < 4; t++)
        #pragma unroll
        for (int e = 0; e < 4; e++)
            acc[t][e] = 0ull;

    #pragma unroll 1
    for (int c = 0; c < NCH; ++c) {
        const int cf = c + PRO;
        if (cf < NCH) {
            const uint32_t sb = (uint32_t)(cf % STAGES) * stage_b;
            cp16(dx + sb,          srcx + cf * CH4);
            cp16(dx + sb + 8 * 16, srcx + cf * CH4 + 8);
            cp16(dw + sb,          srcw + cf * CH4);
            cp16(dw + sb + 8 * 16, srcw + cf * CH4 + 8);
        }
        asm volatile("cp.async.commit_group;" ::: "memory");
        asm volatile("cp.async.wait_group %0;" :: "n"(PRO - 1) : "memory");
        __syncthreads();

        const int st = c % STAGES;
        #pragma unroll
        for (int jj = 0; jj < 2; ++jj) {
            const int c4 = 4 * wid + 2 * jj + ch;   // this lane's float4 col
            const ulonglong2 a0 = xs[st][4 * tg + 0][c4];
            const ulonglong2 a1 = xs[st][4 * tg + 1][c4];
            const ulonglong2 a2 = xs[st][4 * tg + 2][c4];
            const ulonglong2 a3 = xs[st][4 * tg + 3][c4];
            #pragma unroll
            for (int e = 0; e < 4; e++) {
                const ulonglong2 b = ws[st][4 * eg + e][c4];
                fma2(acc[0][e], a0.x, b.x); fma2(acc[0][e], a0.y, b.y);
                fma2(acc[1][e], a1.x, b.x); fma2(acc[1][e], a1.y, b.y);
                fma2(acc[2][e], a2.x, b.x); fma2(acc[2][e], a2.y, b.y);
                fma2(acc[3][e], a3.x, b.x); fma2(acc[3][e], a3.y, b.y);
            }
        }
    }

    // ---- epilogue: collapse packed halves, then col-partials ----
    float lgp[4][4];
    #pragma unroll
    for (int t = 0; t < 4; t++)
        #pragma unroll
        for (int e = 0; e < 4; e++)
            lgp[t][e] = lo_f(acc[t][e]) + hi_f(acc[t][e]);

    // combine the two col-halves (partner lane differs only in ch bit)
    #pragma unroll
    for (int t = 0; t < 4; t++)
        #pragma unroll
        for (int e = 0; e < 4; e++)
            lgp[t][e] += __shfl_xor_sync(0xffffffffu, lgp[t][e], 1);

    // all warps finished reading the ring -> safe to overlay scratch on xs
    __syncthreads();
    float* red = reinterpret_cast<float*>(&xs[0][0][0]); // [4 warps][16 tok][16 exp]
    if (ch == 0) {
        #pragma unroll
        for (int t = 0; t < 4; t++)
            #pragma unroll
            for (int e = 0; e < 4; e++)
                red[(wid * TOKC + 4 * tg + t) * NE + (4 * eg + e)] = lgp[t][e];
    }
    __syncthreads();

    // threads 0..15: one token each — sum 4 warp-partials, top-4, renorm, store
    const int token = ct0 + tid;
    if (tid < TOKC && token < T) {
        float mylg[NE];
        #pragma unroll
        for (int e = 0; e < NE; e++)
            mylg[e] = red[(0 * TOKC + tid) * NE + e]
                    + red[(1 * TOKC + tid) * NE + e]
                    + red[(2 * TOKC + tid) * NE + e]
                    + red[(3 * TOKC + tid) * NE + e];

        // Top-4, stable (strict '>' picks lowest index on ties, matching jax).
        unsigned mask = 0;
        float tw[4];
        int   ti[4];
        #pragma unroll
        for (int k = 0; k < 4; k++) {
            float best = -3.402823466e38f;
            int bi = 0;
            #pragma unroll
            for (int e = 0; e < NE; e++) {
                bool ok = (((mask >> e) & 1u) == 0u) && (mylg[e] > best);
                if (ok) { best = mylg[e]; bi = e; }
            }
            tw[k] = best; ti[k] = bi;
            mask |= (1u << bi);
        }
        // Softmax denominator cancels against p=1 renorm.
        const float m = tw[0];
        float s = 0.f;
        #pragma unroll
        for (int k = 0; k < 4; k++) { tw[k] = expf(tw[k] - m); s += tw[k]; }
        const float inv = 1.0f / s;
        #pragma unroll
        for (int k = 0; k < 4; k++) {
            out[token * 4 + k] = tw[k] * inv;
            if (idx_off >= 0) out[idx_off + token * 4 + k] = (float)ti[k];
        }
    }
}

extern "C" void kernel_launch(void* const* d_in, const int* in_sizes, int n_in,
                              void* d_out, int out_size)
{
    const float* x = (const float*)d_in[0];
    const float* w = (const float*)d_in[1];

    const int H  = in_sizes[1] / NE;     // 6144
    const int T  = in_sizes[0] / H;      // 8192
    const int H4 = H / 4;                // 1536 float4 per row

    const int idx_off = (out_size >= T * 8) ? (T * 4) : -1;

    const int blocks = (T + TOKC - 1) / TOKC;   // 512 CTAs of 128 threads
    router_kernel<<<blocks, 128>>>(x, w, (float*)d_out, T, H4, idx_off);
}

// round 14
// speedup vs baseline: 1.6738x; 1.6738x over previous
#include <cuda_runtime.h>
#include <cstdint>

// DbrxRouter: x[T,H] fp32 @ W[E=16,H]^T -> logits; softmax -> top4 -> /sum(top4)
// Outputs concatenated float32: weights [T,4] then indices [T,4] (as float).
//
// CTA = 128 thr / 4 warps / 16 tokens. Dual cp.async rings (x and W).
// Warps are COLUMN-sliced (warp w owns float4 cols 4w..4w+3 of each chunk for
// all 16 tokens x 16 experts); lane = (eg,tg,ch) 4x4 register tile.
// XOR SWIZZLE: 16B unit (row,col) stored at col ^ (row & 15). This puts the 8
// distinct addresses of every x/W LDS.128 into 8 distinct bank quads ->
// conflict-free single-wavefront 4-way-broadcast loads (R13 had 4-way bank
// conflicts from the 256B row stride). CTA-chunk LDS wavefronts: 160 -> 64.

#define NE      16
#define TOKC    16            // tokens per CTA
#define STAGES  5
#define PRO     3             // prologue depth
#define CH4     16            // float4 per row per chunk (256B)
#define STG_B   4096          // bytes per stage (16 rows x 256B)

__device__ __forceinline__ void fma2(unsigned long long& d,
                                     unsigned long long a,
                                     unsigned long long b) {
    asm("fma.rn.f32x2 %0, %1, %2, %0;" : "+l"(d) : "l"(a), "l"(b));
}
__device__ __forceinline__ float lo_f(unsigned long long v) {
    return __uint_as_float((unsigned)(v & 0xffffffffull));
}
__device__ __forceinline__ float hi_f(unsigned long long v) {
    return __uint_as_float((unsigned)(v >> 32));
}
__device__ __forceinline__ void cp16(uint32_t dst, const void* src) {
    asm volatile("cp.async.cg.shared.global [%0], [%1], 16;"
                 :: "r"(dst), "l"(src) : "memory");
}

__global__ __launch_bounds__(128, 4)
void router_kernel(const float* __restrict__ x, const float* __restrict__ w,
                   float* __restrict__ out, int T, int H4, int idx_off)
{
    // 5 x (4KB x + 4KB W) = 40KB. xs doubles as epilogue scratch afterwards.
    __shared__ __align__(16) ulonglong2 xs[STAGES][TOKC][CH4];
    __shared__ __align__(16) ulonglong2 ws[STAGES][NE][CH4];

    const int tid  = threadIdx.x;
    const int wid  = tid >> 5;
    const int lane = tid & 31;
    const int eg   = lane >> 3;          // expert group: experts 4*eg..4*eg+3
    const int tg   = (lane >> 1) & 3;    // token group:  tokens  4*tg..4*tg+3
    const int ch   = lane & 1;           // col half within warp's slice
    const int ct0  = blockIdx.x * TOKC;
    if (ct0 >= T) return;

    const ulonglong2* __restrict__ x2 = reinterpret_cast<const ulonglong2*>(x);
    const ulonglong2* __restrict__ w2 = reinterpret_cast<const ulonglong2*>(w);

    // ---- producer mapping: thread -> row crow, cols coff and coff+8 ----
    const int crow = tid >> 3;           // 0..15 (token slot / W row)
    const int coff = tid & 7;            // 0..7
    const ulonglong2* srcx = x2 + (size_t)min(ct0 + crow, T - 1) * H4 + coff;
    const ulonglong2* srcw = w2 + (size_t)crow * H4 + coff;

    const uint32_t xbase = (uint32_t)__cvta_generic_to_shared(&xs[0][0][0]);
    const uint32_t wbase = (uint32_t)__cvta_generic_to_shared(&ws[0][0][0]);
    // swizzled smem write offsets (16B units): col' = col ^ (row & 15)
    const int sw0 = (crow * CH4 + ((coff    ) ^ crow)) * 16;
    const int sw1 = (crow * CH4 + ((coff + 8) ^ crow)) * 16;

    const int NCH = H4 / CH4;            // 96 chunks

    // ---- consumer per-lane swizzled byte offsets (precomputed, 16 ints) ----
    int offx[4][2], offw[4][2];
    #pragma unroll
    for (int t = 0; t < 4; t++) {
        const int row = 4 * tg + t;
        #pragma unroll
        for (int jj = 0; jj < 2; jj++) {
            const int c4 = 4 * wid + 2 * jj + ch;
            offx[t][jj] = (row * CH4 + ((c4 ^ row) & 15)) * 16;
        }
    }
    #pragma unroll
    for (int e = 0; e < 4; e++) {
        const int row = 4 * eg + e;
        #pragma unroll
        for (int jj = 0; jj < 2; jj++) {
            const int c4 = 4 * wid + 2 * jj + ch;
            offw[e][jj] = (row * CH4 + ((c4 ^ row) & 15)) * 16;
        }
    }

    // Prologue: fill PRO stages.
    #pragma unroll
    for (int p = 0; p < PRO; ++p) {
        const uint32_t sb = (uint32_t)p * STG_B;
        cp16(xbase + sb + sw0, srcx + p * CH4);
        cp16(xbase + sb + sw1, srcx + p * CH4 + 8);
        cp16(wbase + sb + sw0, srcw + p * CH4);
        cp16(wbase + sb + sw1, srcw + p * CH4 + 8);
        asm volatile("cp.async.commit_group;" ::: "memory");
    }

    unsigned long long acc[4][4];        // [token-in-group][expert-in-group]
    #pragma unroll
    for (int t = 0; t < 4; t++)
        #pragma unroll
        for (int e = 0; e < 4; e++)
            acc[t][e] = 0ull;

    const char* xc0 = reinterpret_cast<const char*>(&xs[0][0][0]);
    const char* wc0 = reinterpret_cast<const char*>(&ws[0][0][0]);

    #pragma unroll 1
    for (int c = 0; c < NCH; ++c) {
        const int cf = c + PRO;
        if (cf < NCH) {
            const uint32_t sb = (uint32_t)(cf % STAGES) * STG_B;
            cp16(xbase + sb + sw0, srcx + cf * CH4);
            cp16(xbase + sb + sw1, srcx + cf * CH4 + 8);
            cp16(wbase + sb + sw0, srcw + cf * CH4);
            cp16(wbase + sb + sw1, srcw + cf * CH4 + 8);
        }
        asm volatile("cp.async.commit_group;" ::: "memory");
        asm volatile("cp.async.wait_group %0;" :: "n"(PRO - 1) : "memory");
        __syncthreads();

        const char* xst = xc0 + (c % STAGES) * STG_B;
        const char* wst = wc0 + (c % STAGES) * STG_B;
        #pragma unroll
        for (int jj = 0; jj < 2; ++jj) {
            const ulonglong2 a0 = *(const ulonglong2*)(xst + offx[0][jj]);
            const ulonglong2 a1 = *(const ulonglong2*)(xst + offx[1][jj]);
            const ulonglong2 a2 = *(const ulonglong2*)(xst + offx[2][jj]);
            const ulonglong2 a3 = *(const ulonglong2*)(xst + offx[3][jj]);
            #pragma unroll
            for (int e = 0; e < 4; e++) {
                const ulonglong2 b = *(const ulonglong2*)(wst + offw[e][jj]);
                fma2(acc[0][e], a0.x, b.x); fma2(acc[0][e], a0.y, b.y);
                fma2(acc[1][e], a1.x, b.x); fma2(acc[1][e], a1.y, b.y);
                fma2(acc[2][e], a2.x, b.x); fma2(acc[2][e], a2.y, b.y);
                fma2(acc[3][e], a3.x, b.x); fma2(acc[3][e], a3.y, b.y);
            }
        }
    }

    // ---- epilogue: collapse packed halves, then col-partials ----
    float lgp[4][4];
    #pragma unroll
    for (int t = 0; t < 4; t++)
        #pragma unroll
        for (int e = 0; e < 4; e++)
            lgp[t][e] = lo_f(acc[t][e]) + hi_f(acc[t][e]);

    // combine the two col-halves (partner lane differs only in ch bit)
    #pragma unroll
    for (int t = 0; t < 4; t++)
        #pragma unroll
        for (int e = 0; e < 4; e++)
            lgp[t][e] += __shfl_xor_sync(0xffffffffu, lgp[t][e], 1);

    // all warps finished reading the ring -> safe to overlay scratch on xs
    __syncthreads();
    float* red = reinterpret_cast<float*>(&xs[0][0][0]); // [4 warps][16 tok][16 exp]
    if (ch == 0) {
        #pragma unroll
        for (int t = 0; t < 4; t++)
            #pragma unroll
            for (int e = 0; e < 4; e++)
                red[(wid * TOKC + 4 * tg + t) * NE + (4 * eg + e)] = lgp[t][e];
    }
    __syncthreads();

    // threads 0..15: one token each — sum 4 warp-partials, top-4, renorm, store
    const int token = ct0 + tid;
    if (tid < TOKC && token < T) {
        float mylg[NE];
        #pragma unroll
        for (int e = 0; e < NE; e++)
            mylg[e] = red[(0 * TOKC + tid) * NE + e]
                    + red[(1 * TOKC + tid) * NE + e]
                    + red[(2 * TOKC + tid) * NE + e]
                    + red[(3 * TOKC + tid) * NE + e];

        // Top-4, stable (strict '>' picks lowest index on ties, matching jax).
        unsigned mask = 0;
        float tw[4];
        int   ti[4];
        #pragma unroll
        for (int k = 0; k < 4; k++) {
            float best = -3.402823466e38f;
            int bi = 0;
            #pragma unroll
            for (int e = 0; e < NE; e++) {
                bool ok = (((mask >> e) & 1u) == 0u) && (mylg[e] > best);
                if (ok) { best = mylg[e]; bi = e; }
            }
            tw[k] = best; ti[k] = bi;
            mask |= (1u << bi);
        }
        // Softmax denominator cancels against p=1 renorm.
        const float m = tw[0];
        float s = 0.f;
        #pragma unroll
        for (int k = 0; k < 4; k++) { tw[k] = expf(tw[k] - m); s += tw[k]; }
        const float inv = 1.0f / s;
        #pragma unroll
        for (int k = 0; k < 4; k++) {
            out[token * 4 + k] = tw[k] * inv;
            if (idx_off >= 0) out[idx_off + token * 4 + k] = (float)ti[k];
        }
    }
}

extern "C" void kernel_launch(void* const* d_in, const int* in_sizes, int n_in,
                              void* d_out, int out_size)
{
    const float* x = (const float*)d_in[0];
    const float* w = (const float*)d_in[1];

    const int H  = in_sizes[1] / NE;     // 6144
    const int T  = in_sizes[0] / H;      // 8192
    const int H4 = H / 4;                // 1536 float4 per row

    const int idx_off = (out_size >= T * 8) ? (T * 4) : -1;

    const int blocks = (T + TOKC - 1) / TOKC;   // 512 CTAs of 128 threads
    router_kernel<<<blocks, 128>>>(x, w, (float*)d_out, T, H4, idx_off);
}